// round 9
// baseline (speedup 1.0000x reference)
#include <cuda_runtime.h>
#include <cstdint>

#define BB 2048
#define TT 512
#define KK 32
#define JOBS 4
#define FULL 0xFFFFFFFFu
#define NEG_INF (-3.402823466e+38f)

// Schedule: batch indices sorted by descending sequence length (LPT).
__device__ unsigned short g_sched[BB];

// f32x2 packed helpers (sm_100+; FFMA2 is only reachable via PTX)
#define PACK2(out, lo, hi) \
    asm("mov.b64 %0, {%1, %2};" : "=l"(out) : "f"(lo), "f"(hi))
#define UNPACK2(lo, hi, in) \
    asm("mov.b64 {%0, %1}, %2;" : "=f"(lo), "=f"(hi) : "l"(in))
#define ADD2(out, a, b) \
    asm("add.rn.f32x2 %0, %1, %2;" : "=l"(out) : "l"(a), "l"(b))
#define FMA2(acc, a, b) \
    asm("fma.rn.f32x2 %0, %1, %2, %0;" : "+l"(acc) : "l"(a), "l"(b))

// ---------------------------------------------------------------------------
// Pre-pass: counting sort of batch indices by descending length.
// ---------------------------------------------------------------------------
__global__ __launch_bounds__(512)
void sched_kernel(const int* __restrict__ lens)
{
    __shared__ int h[TT + 1];
    __shared__ int sc[TT];
    __shared__ int ctr[TT + 1];

    const int tid = threadIdx.x;

    h[tid] = 0;
    if (tid == 0) h[TT] = 0;
    __syncthreads();

    for (int b = tid; b < BB; b += 512) atomicAdd(&h[lens[b]], 1);
    __syncthreads();

    const int r = tid;
    const int v = h[TT - r];
    sc[r] = v;
    __syncthreads();
#pragma unroll
    for (int d = 1; d < TT; d <<= 1) {
        const int add = (r >= d) ? sc[r - d] : 0;
        __syncthreads();
        sc[r] += add;
        __syncthreads();
    }
    ctr[TT - r] = sc[r] - v;
    __syncthreads();

    for (int b = tid; b < BB; b += 512) {
        const int pos = atomicAdd(&ctr[lens[b]], 1);
        g_sched[pos] = (unsigned short)b;
    }
}

// ---------------------------------------------------------------------------
// Main kernel: one block = 128 threads = 4 warps = 4 batch elements.
// Each warp runs BOTH recurrences (Viterbi + logsumexp) for its job,
// with f32x2-packed adds/fmas in the inner loop.
// ---------------------------------------------------------------------------
__global__ __launch_bounds__(128)
void crf_kernel(const float* __restrict__ pot,
                const float* __restrict__ trans,
                const int*   __restrict__ lens,
                const int*   __restrict__ tags_in,
                float*       __restrict__ out)
{
    __shared__ float s_trans[KK * KK];                 // 4 KB
    __shared__ __align__(16) float s_a[JOBS][2][KK];   // alpha broadcast, double buf
    __shared__ __align__(16) float s_e[JOBS][2][KK];   // exp(beta-m) broadcast
    __shared__ unsigned char s_bp[JOBS][TT][KK];       // 64 KB backpointers
    __shared__ unsigned char s_tg[JOBS][TT];           // decoded tags

    const int tid  = threadIdx.x;
    const int lane = tid & 31;
    const int w    = tid >> 5;
    const int b    = g_sched[blockIdx.x * JOBS + w];   // LPT: adjacent lengths

    for (int i = tid; i < KK * KK; i += 128) s_trans[i] = trans[i];
    __syncthreads();

    const float* potb = pot + (size_t)b * TT * KK;
    const int len = lens[b];

    // Per-lane transition column (kcur = lane), packed in f32x2 pairs,
    // plus its elementwise exp.
    unsigned long long tcp[KK / 2];
    unsigned long long ecp[KK / 2];
#pragma unroll
    for (int i = 0; i < KK / 2; ++i) {
        const float t0 = s_trans[(2 * i    ) * KK + lane];
        const float t1 = s_trans[(2 * i + 1) * KK + lane];
        PACK2(tcp[i], t0, t1);
        const float e0 = expf(t0);
        const float e1 = expf(t1);
        PACK2(ecp[i], e0, e1);
    }

    float alpha = potb[lane];   // Viterbi state
    float beta  = alpha;        // logsumexp state

    // 4-deep prefetch pipeline for the pot stream
    float p0 = potb[(size_t)1 * KK + lane];
    float p1 = potb[(size_t)2 * KK + lane];
    float p2 = potb[(size_t)3 * KK + lane];
    float p3 = potb[(size_t)4 * KK + lane];

#pragma unroll 2
    for (int t = 1; t < len; ++t) {
        const float ptc = p0;
        p0 = p1; p1 = p2; p2 = p3;
        int tn = t + 4; tn = (tn < TT) ? tn : TT - 1;
        p3 = potb[(size_t)tn * KK + lane];

        // stabilizer: warp-uniform lane-0 beta (within ~12 of warp max ->
        // exp(beta-m) <= e^12, no overflow, negligible error)
        const float m = __shfl_sync(FULL, beta, 0);
        const float e = __expf(beta - m);

        float* sa = &s_a[w][t & 1][0];
        float* se = &s_e[w][t & 1][0];
        sa[lane] = alpha;
        se[lane] = e;
        __syncwarp();
        const float4* av = (const float4*)sa;
        const float4* ev = (const float4*)se;

        // Viterbi: 4 blocked argmax chains (chain c covers kp in [8c,8c+8));
        // lse: 4 packed fma accumulator pairs.
        float bv0 = NEG_INF, bv1 = NEG_INF, bv2 = NEG_INF, bv3 = NEG_INF;
        int   bi0 = 0, bi1 = 0, bi2 = 0, bi3 = 0;
        unsigned long long q0 = 0ull, q1 = 0ull, q2 = 0ull, q3 = 0ull;
#pragma unroll
        for (int j = 0; j < 8; ++j) {
            const float4 a4 = av[j];
            const float4 e4 = ev[j];
            const int kb = j * 4;

            unsigned long long a01, a23, e01, e23, s01, s23;
            PACK2(a01, a4.x, a4.y);
            PACK2(a23, a4.z, a4.w);
            PACK2(e01, e4.x, e4.y);
            PACK2(e23, e4.z, e4.w);

            ADD2(s01, a01, tcp[2 * j]);
            ADD2(s23, a23, tcp[2 * j + 1]);
            if (j & 1) { FMA2(q2, e01, ecp[2 * j]); FMA2(q3, e23, ecp[2 * j + 1]); }
            else       { FMA2(q0, e01, ecp[2 * j]); FMA2(q1, e23, ecp[2 * j + 1]); }

            float s0, s1, s2, s3;
            UNPACK2(s0, s1, s01);
            UNPACK2(s2, s3, s23);

            if ((j >> 1) == 0) {
                if (s0 > bv0) { bv0 = s0; bi0 = kb + 0; }
                if (s1 > bv0) { bv0 = s1; bi0 = kb + 1; }
                if (s2 > bv0) { bv0 = s2; bi0 = kb + 2; }
                if (s3 > bv0) { bv0 = s3; bi0 = kb + 3; }
            } else if ((j >> 1) == 1) {
                if (s0 > bv1) { bv1 = s0; bi1 = kb + 0; }
                if (s1 > bv1) { bv1 = s1; bi1 = kb + 1; }
                if (s2 > bv1) { bv1 = s2; bi1 = kb + 2; }
                if (s3 > bv1) { bv1 = s3; bi1 = kb + 3; }
            } else if ((j >> 1) == 2) {
                if (s0 > bv2) { bv2 = s0; bi2 = kb + 0; }
                if (s1 > bv2) { bv2 = s1; bi2 = kb + 1; }
                if (s2 > bv2) { bv2 = s2; bi2 = kb + 2; }
                if (s3 > bv2) { bv2 = s3; bi2 = kb + 3; }
            } else {
                if (s0 > bv3) { bv3 = s0; bi3 = kb + 0; }
                if (s1 > bv3) { bv3 = s1; bi3 = kb + 1; }
                if (s2 > bv3) { bv3 = s2; bi3 = kb + 2; }
                if (s3 > bv3) { bv3 = s3; bi3 = kb + 3; }
            }
        }
        // combine in ascending-kp order with strict > : exact first-index tie-break
        float best = bv0; int bk = bi0;
        if (bv1 > best) { best = bv1; bk = bi1; }
        if (bv2 > best) { best = bv2; bk = bi2; }
        if (bv3 > best) { best = bv3; bk = bi3; }

        float l0, h0, l1, h1, l2, h2, l3, h3;
        UNPACK2(l0, h0, q0);
        UNPACK2(l1, h1, q1);
        UNPACK2(l2, h2, q2);
        UNPACK2(l3, h3, q3);
        const float sum = ((l0 + h0) + (l1 + h1)) + ((l2 + h2) + (l3 + h3));

        alpha = ptc + best;
        beta  = ptc + m + __logf(sum);
        s_bp[w][t][lane] = (unsigned char)bk;
    }

    // ---- Viterbi epilogue: warp argmax over lanes (first index on ties) ----
    float bs = alpha;
    int   bt = lane;
#pragma unroll
    for (int o = 16; o > 0; o >>= 1) {
        const float ov = __shfl_xor_sync(FULL, bs, o);
        const int   oi = __shfl_xor_sync(FULL, bt, o);
        if (ov > bs || (ov == bs && oi < bt)) { bs = ov; bt = oi; }
    }

    __syncwarp();   // all s_bp writes visible to lane 0
    if (lane == 0) {
        unsigned char* st = s_tg[w];
        int carry = bt;
        for (int t = TT - 1; t >= len - 1; --t) st[t] = (unsigned char)carry;
        for (int t = len - 1; t >= 1; --t) {
            carry = s_bp[w][t][carry];
            st[t - 1] = (unsigned char)carry;
        }
    }
    __syncwarp();

    // outputs: tags [B*T] (coalesced), best_score [B]
    for (int t = lane; t < TT; t += 32)
        out[(size_t)b * TT + t] = (float)s_tg[w][t];
    if (lane == 0)
        out[(size_t)BB * TT + b] = bs;

    // ---- lse epilogue: log_norm (full-precision lane reduce) ----
    float m2 = beta;
#pragma unroll
    for (int o = 16; o > 0; o >>= 1)
        m2 = fmaxf(m2, __shfl_xor_sync(FULL, m2, o));
    float s2 = __expf(beta - m2);
#pragma unroll
    for (int o = 16; o > 0; o >>= 1)
        s2 += __shfl_xor_sync(FULL, s2, o);
    const float logZ = m2 + logf(s2);

    // sequence score: unary (t < len) + binary (t < len-1)
    const int* tagb = tags_in + (size_t)b * TT;
    float ss = 0.0f;
    for (int t = lane; t < TT; t += 32) {
        const int tg = tagb[t];
        if (t < len)     ss += potb[(size_t)t * KK + tg];
        if (t + 1 < len) ss += s_trans[tg * KK + tagb[t + 1]];
    }
#pragma unroll
    for (int o = 16; o > 0; o >>= 1)
        ss += __shfl_xor_sync(FULL, ss, o);

    if (lane == 0)
        out[(size_t)BB * TT + BB + b] = ss - logZ;
}

extern "C" void kernel_launch(void* const* d_in, const int* in_sizes, int n_in,
                              void* d_out, int out_size)
{
    const float* potentials       = (const float*)d_in[0];
    const float* transitions      = (const float*)d_in[1];
    const int*   sequence_lengths = (const int*)d_in[2];
    const int*   tag_indices      = (const int*)d_in[3];
    float*       out              = (float*)d_out;

    sched_kernel<<<1, 512>>>(sequence_lengths);
    crf_kernel<<<BB / JOBS, 128>>>(potentials, transitions, sequence_lengths,
                                   tag_indices, out);
}